// round 1
// baseline (speedup 1.0000x reference)
#include <cuda_runtime.h>
#include <cuda_bf16.h>

#define BB   16
#define MM   256
#define NN   8192
#define NFG  128
#define NBG  384
#define SAMP 512

static __device__ __forceinline__ unsigned f2s(float f) {
    unsigned u = __float_as_uint(f);
    return (u & 0x80000000u) ? ~u : (u | 0x80000000u);
}

// Kernel 1: per-proposal max/argmax IoU over the 256 gt boxes of its batch.
__global__ void match_kernel(const float* __restrict__ gt,
                             const float* __restrict__ prop,
                             float* __restrict__ mv,
                             float* __restrict__ mi) {
    int b = blockIdx.y;
    int n = blockIdx.x * blockDim.x + threadIdx.x;
    __shared__ float4 g[MM];
    if (threadIdx.x < MM)
        g[threadIdx.x] = ((const float4*)gt)[b * MM + threadIdx.x];
    __syncthreads();

    float4 p = ((const float4*)prop)[b * NN + n];
    float ap = (p.z - p.x) * (p.w - p.y);
    float best = -1.0f;
    int bi = 0;
#pragma unroll 4
    for (int m = 0; m < MM; ++m) {
        float4 gb = g[m];
        float ag = (gb.z - gb.x) * (gb.w - gb.y);
        float lx = fmaxf(gb.x, p.x), ly = fmaxf(gb.y, p.y);
        float rx = fminf(gb.z, p.z), ry = fminf(gb.w, p.w);
        float w = fmaxf(rx - lx, 0.0f), h = fmaxf(ry - ly, 0.0f);
        float inter = w * h;
        float uni = ag + ap - inter;
        float iou = (uni > 0.0f) ? __fdiv_rn(inter, uni) : 0.0f;
        if (iou > best) { best = iou; bi = m; }   // strict > => first-max (argmax semantics)
    }
    mv[b * NN + n] = best;
    mi[b * NN + n] = (float)bi;
}

// Kernel 2: per (batch, fg/bg) top-k via descending bitonic sort of 64-bit keys.
// key = sortable(priority or NEG) << 32 | (0xFFFFFFFF - idx)
// => descending sort gives priorities desc, ties (all-NEG fill) by ascending idx,
//    exactly matching lax.top_k.
__global__ void sample_kernel(const int*   __restrict__ gtc,
                              const float* __restrict__ pri,
                              const float* __restrict__ mv,
                              const float* __restrict__ mi,
                              float* __restrict__ s_idx,
                              float* __restrict__ s_cls,
                              float* __restrict__ s_gt) {
    extern __shared__ unsigned long long keys[];
    const int b = blockIdx.x;
    const bool wantFg = (blockIdx.y == 0);
    const int tid = threadIdx.x;
    const unsigned negs = f2s(-1e30f);

    // Build keys
    for (int t = tid; t < NN; t += blockDim.x) {
        bool fg = mv[b * NN + t] >= 0.5f;
        bool sel = (fg == wantFg);
        unsigned u = sel ? f2s(pri[b * NN + t]) : negs;
        keys[t] = ((unsigned long long)u << 32) |
                  (unsigned long long)(0xFFFFFFFFu - (unsigned)t);
    }
    __syncthreads();

    // Descending bitonic sort of 8192 keys
    for (int k = 2; k <= NN; k <<= 1) {
        for (int j = k >> 1; j > 0; j >>= 1) {
            for (int t = tid; t < NN; t += blockDim.x) {
                int p = t ^ j;
                if (p > t) {
                    unsigned long long a = keys[t], c = keys[p];
                    bool sw = ((t & k) == 0) ? (a < c) : (a > c);
                    if (sw) { keys[t] = c; keys[p] = a; }
                }
            }
            __syncthreads();
        }
    }

    // Emit top-K
    const int K   = wantFg ? NFG : NBG;
    const int off = wantFg ? 0   : NFG;
    for (int jj = tid; jj < K; jj += blockDim.x) {
        unsigned long long key = keys[jj];
        unsigned u = (unsigned)(key >> 32);
        int idx = (int)(0xFFFFFFFFu - (unsigned)(key & 0xFFFFFFFFull));
        bool valid = u > negs;                // matches reference: top > NEG (strict)
        s_idx[b * SAMP + off + jj] = (float)idx;
        float clsv, gtv;
        if (!valid) {
            clsv = -1.0f; gtv = -1.0f;
        } else {
            int midx = (int)mi[b * NN + idx];
            gtv = (float)midx;
            clsv = wantFg ? (float)gtc[b * MM + midx] : 80.0f;
        }
        s_cls[b * SAMP + off + jj] = clsv;
        s_gt [b * SAMP + off + jj] = gtv;
    }
}

extern "C" void kernel_launch(void* const* d_in, const int* in_sizes, int n_in,
                              void* d_out, int out_size) {
    const float* gt_boxes   = (const float*)d_in[0];   // [B,M,4]
    const int*   gt_classes = (const int*)  d_in[1];   // [B,M]
    const float* prop_boxes = (const float*)d_in[2];   // [B,N,4]
    const float* rand_pri   = (const float*)d_in[3];   // [B,N]

    float* out = (float*)d_out;
    float* matched_vals = out;                        // B*N
    float* matched_idxs = out + BB * NN;              // B*N
    float* sampled_idxs = out + 2 * BB * NN;          // B*512
    float* sampled_cls  = sampled_idxs + BB * SAMP;   // B*512
    float* sampled_gt   = sampled_cls  + BB * SAMP;   // B*512

    dim3 g1(NN / 256, BB);
    match_kernel<<<g1, 256>>>(gt_boxes, prop_boxes, matched_vals, matched_idxs);

    cudaFuncSetAttribute(sample_kernel,
                         cudaFuncAttributeMaxDynamicSharedMemorySize, NN * 8);
    dim3 g2(BB, 2);
    sample_kernel<<<g2, 1024, NN * 8>>>(gt_classes, rand_pri,
                                        matched_vals, matched_idxs,
                                        sampled_idxs, sampled_cls, sampled_gt);
}

// round 4
// speedup vs baseline: 4.1705x; 4.1705x over previous
#include <cuda_runtime.h>
#include <cuda_bf16.h>

#define BB    16
#define MM    256
#define NN    8192
#define NFG   128
#define NBG   384
#define SAMP  512
#define NBINS 256
#define LISTCAP 2048

static __device__ __forceinline__ unsigned f2s(float f) {
    unsigned u = __float_as_uint(f);
    return (u & 0x80000000u) ? ~u : (u | 0x80000000u);
}

// ---------------------------------------------------------------------------
// Kernel 1: per-proposal max/argmax IoU over 256 gt boxes. 2 proposals/thread.
// Argmax via exact cross-multiplication; one precise division at the end.
// (Verified bit-exact vs reference in R2.)
// ---------------------------------------------------------------------------
__global__ void match_kernel(const float4* __restrict__ gt,
                             const float4* __restrict__ prop,
                             float* __restrict__ mv,
                             float* __restrict__ mi) {
    const int b = blockIdx.y;
    __shared__ float4 g[MM];
    __shared__ float  ga[MM];
    const int tid = threadIdx.x;  // 256
    {
        float4 v = gt[b * MM + tid];
        g[tid] = v;
        ga[tid] = __fmul_rn(v.z - v.x, v.w - v.y);
    }
    __syncthreads();

    const int n0 = blockIdx.x * 512 + tid;
    const int n1 = n0 + 256;
    float4 p0 = prop[b * NN + n0];
    float4 p1 = prop[b * NN + n1];
    float ap0 = __fmul_rn(p0.z - p0.x, p0.w - p0.y);
    float ap1 = __fmul_rn(p1.z - p1.x, p1.w - p1.y);

    float bI0 = -1.0f, bU0 = 1.0f, bI1 = -1.0f, bU1 = 1.0f;
    int bx0 = 0, bx1 = 0;

#pragma unroll 8
    for (int m = 0; m < MM; ++m) {
        float4 gb = g[m];
        float a = ga[m];
        {
            float lx = fmaxf(gb.x, p0.x), ly = fmaxf(gb.y, p0.y);
            float rx = fminf(gb.z, p0.z), ry = fminf(gb.w, p0.w);
            float w = fmaxf(rx - lx, 0.0f), h = fmaxf(ry - ly, 0.0f);
            float inter = __fmul_rn(w, h);
            float uni = __fsub_rn(__fadd_rn(a, ap0), inter);
            if (__fmul_rn(inter, bU0) > __fmul_rn(bI0, uni)) {
                bI0 = inter; bU0 = uni; bx0 = m;
            }
        }
        {
            float lx = fmaxf(gb.x, p1.x), ly = fmaxf(gb.y, p1.y);
            float rx = fminf(gb.z, p1.z), ry = fminf(gb.w, p1.w);
            float w = fmaxf(rx - lx, 0.0f), h = fmaxf(ry - ly, 0.0f);
            float inter = __fmul_rn(w, h);
            float uni = __fsub_rn(__fadd_rn(a, ap1), inter);
            if (__fmul_rn(inter, bU1) > __fmul_rn(bI1, uni)) {
                bI1 = inter; bU1 = uni; bx1 = m;
            }
        }
    }
    mv[b * NN + n0] = __fdiv_rn(bI0, bU0);
    mi[b * NN + n0] = (float)bx0;
    mv[b * NN + n1] = __fdiv_rn(bI1, bU1);
    mi[b * NN + n1] = (float)bx1;
}

// ---------------------------------------------------------------------------
// Kernel 2: per (batch, fg/bg) top-K via VALUE-binned histogram selection.
// bin = (int)(p*256): uniform for uniform p => threshold bin ~32 elems,
// candidate list ~K+40 << LISTCAP. Ranking uses full 64-bit sortable keys
// (exact); binning only localizes. key = f2s(pri)<<32 | ~idx.
// ---------------------------------------------------------------------------
__global__ void sample_kernel(const int*   __restrict__ gtc,
                              const float* __restrict__ pri,
                              const float* __restrict__ mv,
                              const float* __restrict__ mi,
                              float* __restrict__ s_idx,
                              float* __restrict__ s_cls,
                              float* __restrict__ s_gt) {
    __shared__ unsigned u_arr[NN];          // sortable pri if selected, else 0
    __shared__ unsigned char bin_arr[NN];   // value bin (only valid if selected)
    __shared__ unsigned hist[NBINS];
    __shared__ unsigned suf[NBINS];
    __shared__ unsigned long long list[LISTCAP];
    __shared__ unsigned scanbuf[1024];
    __shared__ int listCnt, sh_T, sh_total;

    const int b = blockIdx.x;
    const bool wantFg = (blockIdx.y == 0);
    const int K   = wantFg ? NFG : NBG;
    const int off = wantFg ? 0   : NFG;
    const int tid = threadIdx.x;            // 1024

    if (tid < NBINS) hist[tid] = 0;
    if (tid == 0) { listCnt = 0; sh_T = 0; }
    __syncthreads();

    // 1. build selection keys + value histogram
    for (int t = tid; t < NN; t += 1024) {
        bool sel = ((mv[b * NN + t] >= 0.5f) == wantFg);
        unsigned u = 0;
        unsigned bn = 0;
        if (sel) {
            float p = pri[b * NN + t];
            u = f2s(p);                     // >= 0x80000000 for p in [0,1)
            bn = (unsigned)(p * 256.0f);    // uniform bins, p<1 => bn<256
            if (bn > 255u) bn = 255u;
            atomicAdd(&hist[bn], 1u);
        }
        u_arr[t] = u;
        bin_arr[t] = (unsigned char)bn;
    }
    __syncthreads();

    // 2. suffix sum over bins
    if (tid < NBINS) suf[tid] = hist[tid];
    __syncthreads();
    for (int d = 1; d < NBINS; d <<= 1) {
        unsigned add = 0;
        if (tid < NBINS && tid + d < NBINS) add = suf[tid + d];
        __syncthreads();
        if (tid < NBINS) suf[tid] += add;
        __syncthreads();
    }
    if (tid == 0) sh_total = (int)suf[0];
    if (tid < NBINS) {
        unsigned above = (tid + 1 < NBINS) ? suf[tid + 1] : 0;
        if ((int)suf[tid] >= K && (int)above < K) sh_T = tid;   // unique; 0 if total<K
    }
    __syncthreads();

    // 3. compact candidates (bin >= T) with warp-aggregated atomics
    const int T = sh_T;
    const int lane = tid & 31;
    for (int t = tid; t < NN; t += 1024) {
        unsigned u = u_arr[t];
        bool take = (u != 0) && ((int)bin_arr[t] >= T);
        unsigned ball = __ballot_sync(0xffffffffu, take);
        int base = 0;
        int leader = __ffs(ball) - 1;
        if (ball) {
            if (lane == leader) base = atomicAdd(&listCnt, __popc(ball));
            base = __shfl_sync(0xffffffffu, base, leader);
        }
        if (take) {
            int pos = base + __popc(ball & ((1u << lane) - 1u));
            if (pos < LISTCAP)
                list[pos] = ((unsigned long long)u << 32) |
                            (unsigned long long)(0xFFFFFFFFu - (unsigned)t);
        }
    }
    __syncthreads();

    // 4. rank candidates by counting larger keys; write winners at their rank
    int S = listCnt < LISTCAP ? listCnt : LISTCAP;
    for (int i = tid; i < S; i += 1024) {
        unsigned long long ki = list[i];
        int rank = 0;
        for (int j = 0; j < S; ++j) rank += (list[j] > ki);
        if (rank < K) {
            int idx = (int)(0xFFFFFFFFu - (unsigned)(ki & 0xFFFFFFFFull));
            int midx = (int)mi[b * NN + idx];
            s_idx[b * SAMP + off + rank] = (float)idx;
            s_gt [b * SAMP + off + rank] = (float)midx;
            s_cls[b * SAMP + off + rank] = wantFg ? (float)gtc[b * MM + midx] : 80.0f;
        }
    }
    __syncthreads();

    // 5. fill tail slots (total < K) with not-selected indices, ascending
    const int total = sh_total;
    if (total < K) {
        const int need = K - total;
        const int base_e = tid * (NN / 1024);     // contiguous chunk of 8
        unsigned msk = 0;
        int c = 0;
        for (int e = 0; e < NN / 1024; ++e) {
            if (u_arr[base_e + e] == 0) { msk |= 1u << e; ++c; }
        }
        scanbuf[tid] = (unsigned)c;
        __syncthreads();
        for (int d = 1; d < 1024; d <<= 1) {
            unsigned v = (tid >= d) ? scanbuf[tid - d] : 0;
            __syncthreads();
            scanbuf[tid] += v;
            __syncthreads();
        }
        int p = (int)scanbuf[tid] - c;            // exclusive prefix
        for (int e = 0; e < NN / 1024; ++e) {
            if (msk & (1u << e)) {
                if (p < need) {
                    int slot = b * SAMP + off + total + p;
                    s_idx[slot] = (float)(base_e + e);
                    s_cls[slot] = -1.0f;
                    s_gt [slot] = -1.0f;
                }
                ++p;
            }
        }
    }
}

extern "C" void kernel_launch(void* const* d_in, const int* in_sizes, int n_in,
                              void* d_out, int out_size) {
    const float* gt_boxes   = (const float*)d_in[0];   // [B,M,4]
    const int*   gt_classes = (const int*)  d_in[1];   // [B,M]
    const float* prop_boxes = (const float*)d_in[2];   // [B,N,4]
    const float* rand_pri   = (const float*)d_in[3];   // [B,N]

    float* out = (float*)d_out;
    float* matched_vals = out;                        // B*N
    float* matched_idxs = out + BB * NN;              // B*N
    float* sampled_idxs = out + 2 * BB * NN;          // B*512
    float* sampled_cls  = sampled_idxs + BB * SAMP;   // B*512
    float* sampled_gt   = sampled_cls  + BB * SAMP;   // B*512

    dim3 g1(NN / 512, BB);
    match_kernel<<<g1, 256>>>((const float4*)gt_boxes, (const float4*)prop_boxes,
                              matched_vals, matched_idxs);

    dim3 g2(BB, 2);
    sample_kernel<<<g2, 1024>>>(gt_classes, rand_pri,
                                matched_vals, matched_idxs,
                                sampled_idxs, sampled_cls, sampled_gt);
}

// round 7
// speedup vs baseline: 4.4109x; 1.0576x over previous
#include <cuda_runtime.h>
#include <cuda_bf16.h>

#define BB    16
#define MM    256
#define NN    8192
#define NFG   128
#define NBG   384
#define SAMP  512
#define NBINS 256
#define LISTCAP 2048

__device__ unsigned g_keyFg[BB * NN];          // f2s(pri) if fg else 0
__device__ unsigned g_keyBg[BB * NN];          // f2s(pri) if bg else 0
__device__ unsigned g_hist[2 * BB * NBINS];    // [side][b][bin]; zeroed by sample at end

static __device__ __forceinline__ unsigned f2s(float f) {
    unsigned u = __float_as_uint(f);
    return (u & 0x80000000u) ? ~u : (u | 0x80000000u);
}

// ---------------------------------------------------------------------------
// Kernel 1: max/argmax IoU (bit-exact cross-mult scheme, proven rel_err=0)
// + emits sortable keys and global per-(side,b) value histograms.
// ---------------------------------------------------------------------------
__global__ void match_kernel(const float4* __restrict__ gt,
                             const float4* __restrict__ prop,
                             const float*  __restrict__ pri,
                             float* __restrict__ mv,
                             float* __restrict__ mi) {
    const int b = blockIdx.y;
    __shared__ float4 g[MM];
    __shared__ float  ga[MM];
    const int tid = threadIdx.x;  // 256
    {
        float4 v = gt[b * MM + tid];
        g[tid] = v;
        ga[tid] = __fmul_rn(v.z - v.x, v.w - v.y);
    }
    __syncthreads();

    const int n0 = blockIdx.x * 512 + tid;
    const int n1 = n0 + 256;
    float4 p0 = prop[b * NN + n0];
    float4 p1 = prop[b * NN + n1];
    float pr0 = pri[b * NN + n0];
    float pr1 = pri[b * NN + n1];
    float ap0 = __fmul_rn(p0.z - p0.x, p0.w - p0.y);
    float ap1 = __fmul_rn(p1.z - p1.x, p1.w - p1.y);

    float bI0 = -1.0f, bU0 = 1.0f, bI1 = -1.0f, bU1 = 1.0f;
    int bx0 = 0, bx1 = 0;

#pragma unroll 8
    for (int m = 0; m < MM; ++m) {
        float4 gb = g[m];
        float a = ga[m];
        {
            float lx = fmaxf(gb.x, p0.x), ly = fmaxf(gb.y, p0.y);
            float rx = fminf(gb.z, p0.z), ry = fminf(gb.w, p0.w);
            float w = fmaxf(rx - lx, 0.0f), h = fmaxf(ry - ly, 0.0f);
            float inter = __fmul_rn(w, h);
            float uni = __fsub_rn(__fadd_rn(a, ap0), inter);
            if (__fmul_rn(inter, bU0) > __fmul_rn(bI0, uni)) {
                bI0 = inter; bU0 = uni; bx0 = m;
            }
        }
        {
            float lx = fmaxf(gb.x, p1.x), ly = fmaxf(gb.y, p1.y);
            float rx = fminf(gb.z, p1.z), ry = fminf(gb.w, p1.w);
            float w = fmaxf(rx - lx, 0.0f), h = fmaxf(ry - ly, 0.0f);
            float inter = __fmul_rn(w, h);
            float uni = __fsub_rn(__fadd_rn(a, ap1), inter);
            if (__fmul_rn(inter, bU1) > __fmul_rn(bI1, uni)) {
                bI1 = inter; bU1 = uni; bx1 = m;
            }
        }
    }
    float v0 = __fdiv_rn(bI0, bU0);
    float v1 = __fdiv_rn(bI1, bU1);
    mv[b * NN + n0] = v0;  mi[b * NN + n0] = (float)bx0;
    mv[b * NN + n1] = v1;  mi[b * NN + n1] = (float)bx1;

    // keys + histograms
    {
        bool fg = (v0 >= 0.5f);
        unsigned u = f2s(pr0);
        unsigned bn = (unsigned)(pr0 * 256.0f); if (bn > 255u) bn = 255u;
        g_keyFg[b * NN + n0] = fg ? u : 0u;
        g_keyBg[b * NN + n0] = fg ? 0u : u;
        atomicAdd(&g_hist[(fg ? 0 : 1) * BB * NBINS + b * NBINS + bn], 1u);
    }
    {
        bool fg = (v1 >= 0.5f);
        unsigned u = f2s(pr1);
        unsigned bn = (unsigned)(pr1 * 256.0f); if (bn > 255u) bn = 255u;
        g_keyFg[b * NN + n1] = fg ? u : 0u;
        g_keyBg[b * NN + n1] = fg ? 0u : u;
        atomicAdd(&g_hist[(fg ? 0 : 1) * BB * NBINS + b * NBINS + bn], 1u);
    }
}

// ---------------------------------------------------------------------------
// Kernel 2: per (batch, side) exact top-K from precomputed keys + histogram.
// ---------------------------------------------------------------------------
__global__ void sample_kernel(const int*   __restrict__ gtc,
                              const float* __restrict__ mi,
                              float* __restrict__ s_idx,
                              float* __restrict__ s_cls,
                              float* __restrict__ s_gt) {
    __shared__ unsigned long long list[LISTCAP];
    __shared__ unsigned warpsum[32];
    __shared__ int listCnt, sh_T, sh_total;

    const int b = blockIdx.x;
    const bool wantFg = (blockIdx.y == 0);
    const int K   = wantFg ? NFG : NBG;
    const int off = wantFg ? 0   : NFG;
    const int tid = threadIdx.x;            // 1024
    const int lane = tid & 31;
    const int wid  = tid >> 5;

    const unsigned* keys = (wantFg ? g_keyFg : g_keyBg) + b * NN;
    unsigned* histSlice = &g_hist[(wantFg ? 0 : 1) * BB * NBINS + b * NBINS];

    // Load this thread's 8 contiguous keys into registers (coalesced LDG.128 x2)
    unsigned u[8];
    {
        const uint4* k4 = (const uint4*)(keys + tid * 8);
        uint4 a = k4[0], c = k4[1];
        u[0] = a.x; u[1] = a.y; u[2] = a.z; u[3] = a.w;
        u[4] = c.x; u[5] = c.y; u[6] = c.z; u[7] = c.w;
    }

    if (tid == 0) listCnt = 0;

    // Warp 0: suffix-scan histogram, find threshold bin T and total
    if (wid == 0) {
        unsigned h[8];
#pragma unroll
        for (int e = 0; e < 8; ++e) h[e] = histSlice[lane * 8 + e];
        unsigned lsum = 0;
#pragma unroll
        for (int e = 0; e < 8; ++e) lsum += h[e];
        unsigned s = lsum;
#pragma unroll
        for (int d = 1; d < 32; d <<= 1) {
            unsigned v = __shfl_down_sync(0xffffffffu, s, d);
            if (lane + d < 32) s += v;
        }
        unsigned total = __shfl_sync(0xffffffffu, s, 0);
        unsigned excl = s - lsum;               // suffix over lanes > lane
        unsigned run = excl;
        int myT = 0;
#pragma unroll
        for (int e = 7; e >= 0; --e) {
            unsigned sufE = run + h[e];
            if ((int)sufE >= K && (int)run < K) myT = lane * 8 + e;
            run = sufE;
        }
#pragma unroll
        for (int d = 1; d < 32; d <<= 1) {
            int v = __shfl_xor_sync(0xffffffffu, myT, d);
            if (v > myT) myT = v;
        }
        if (lane == 0) { sh_T = myT; sh_total = (int)total; }
    }
    __syncthreads();

    const int T = sh_T;
    const int total = sh_total;

    // Compact candidates (bin >= T): one atomic per warp
    {
        unsigned ball[8];
        bool take[8];
        unsigned cnt = 0;
#pragma unroll
        for (int e = 0; e < 8; ++e) {
            bool tk = false;
            if (u[e] != 0u) {
                float p = __uint_as_float(u[e] ^ 0x80000000u);
                unsigned bn = (unsigned)(p * 256.0f); if (bn > 255u) bn = 255u;
                tk = ((int)bn >= T);
            }
            take[e] = tk;
            ball[e] = __ballot_sync(0xffffffffu, tk);
            cnt += __popc(ball[e]);
        }
        int base = 0;
        if (lane == 0 && cnt) base = atomicAdd(&listCnt, (int)cnt);
        base = __shfl_sync(0xffffffffu, base, 0);
        unsigned pre = 0;
        const unsigned lmask = (lane == 0) ? 0u : (0xffffffffu >> (32 - lane));
#pragma unroll
        for (int e = 0; e < 8; ++e) {
            if (take[e]) {
                int pos = base + (int)pre + __popc(ball[e] & lmask);
                if (pos < LISTCAP) {
                    int t = tid * 8 + e;
                    list[pos] = ((unsigned long long)u[e] << 32) |
                                (unsigned long long)(0xFFFFFFFFu - (unsigned)t);
                }
            }
            pre += __popc(ball[e]);
        }
    }
    __syncthreads();

    // Rank candidates exactly; write winners at their rank
    int S = listCnt < LISTCAP ? listCnt : LISTCAP;
    if (tid < S) {
        unsigned long long ki = list[tid];
        int rank = 0;
        for (int j = 0; j < S; ++j) rank += (list[j] > ki);
        if (rank < K) {
            int idx = (int)(0xFFFFFFFFu - (unsigned)(ki & 0xFFFFFFFFull));
            int midx = (int)mi[b * NN + idx];
            s_idx[b * SAMP + off + rank] = (float)idx;
            s_gt [b * SAMP + off + rank] = (float)midx;
            s_cls[b * SAMP + off + rank] = wantFg ? (float)gtc[b * MM + midx] : 80.0f;
        }
    }

    // Fill tail (total < K) with not-selected indices, ascending
    if (total < K) {
        const int need = K - total;
        unsigned msk = 0; int c = 0;
#pragma unroll
        for (int e = 0; e < 8; ++e)
            if (u[e] == 0u) { msk |= 1u << e; ++c; }
        // warp inclusive scan of c
        int inc = c;
#pragma unroll
        for (int d = 1; d < 32; d <<= 1) {
            int v = __shfl_up_sync(0xffffffffu, inc, d);
            if (lane >= d) inc += v;
        }
        if (lane == 31) warpsum[wid] = (unsigned)inc;
        __syncthreads();
        if (wid == 0) {
            int wv = (int)warpsum[lane];
            int winc = wv;
#pragma unroll
            for (int d = 1; d < 32; d <<= 1) {
                int v = __shfl_up_sync(0xffffffffu, winc, d);
                if (lane >= d) winc += v;
            }
            warpsum[lane] = (unsigned)(winc - wv);   // exclusive warp offset
        }
        __syncthreads();
        int p = (int)warpsum[wid] + (inc - c);       // global exclusive prefix
        const int base_e = tid * 8;
#pragma unroll
        for (int e = 0; e < 8; ++e) {
            if (msk & (1u << e)) {
                if (p < need) {
                    int slot = b * SAMP + off + total + p;
                    s_idx[slot] = (float)(base_e + e);
                    s_cls[slot] = -1.0f;
                    s_gt [slot] = -1.0f;
                }
                ++p;
            }
        }
    }
    __syncthreads();

    // Zero this block's histogram slice for the next launch
    if (tid < NBINS) histSlice[tid] = 0u;
}

extern "C" void kernel_launch(void* const* d_in, const int* in_sizes, int n_in,
                              void* d_out, int out_size) {
    const float* gt_boxes   = (const float*)d_in[0];   // [B,M,4]
    const int*   gt_classes = (const int*)  d_in[1];   // [B,M]
    const float* prop_boxes = (const float*)d_in[2];   // [B,N,4]
    const float* rand_pri   = (const float*)d_in[3];   // [B,N]

    float* out = (float*)d_out;
    float* matched_vals = out;                        // B*N
    float* matched_idxs = out + BB * NN;              // B*N
    float* sampled_idxs = out + 2 * BB * NN;          // B*512
    float* sampled_cls  = sampled_idxs + BB * SAMP;   // B*512
    float* sampled_gt   = sampled_cls  + BB * SAMP;   // B*512

    dim3 g1(NN / 512, BB);
    match_kernel<<<g1, 256>>>((const float4*)gt_boxes, (const float4*)prop_boxes,
                              rand_pri, matched_vals, matched_idxs);

    dim3 g2(BB, 2);
    sample_kernel<<<g2, 1024>>>(gt_classes, matched_idxs,
                                sampled_idxs, sampled_cls, sampled_gt);
}